// round 9
// baseline (speedup 1.0000x reference)
#include <cuda_runtime.h>
#include <cuda_bf16.h>
#include <cstdint>

#define BB 32
#define NI 1024
#define DIN 1024
#define NOUT 64
#define DOUT 1024

// ---------------- device scratch ----------------
__device__ float g_faT[NI * BB];              // f_a transposed [i][b]
__device__ float g_xout0[BB * NOUT * DOUT];   // iter-0 output [b][j][h]
__device__ float g_pred[BB * NOUT * DIN];     // pred [b][j][d]
__device__ float g_phi1[BB * NI * NOUT];      // phi iter-1 [b][i][j]
__device__ float g_phiT[NOUT * NI * BB];      // phi transposed [j][i][b]
__device__ float g_ppart[4][BB * NOUT * DIN]; // k_pred split-K partials

// ---------------- mma helpers ----------------
__device__ __forceinline__ uint32_t smem_u32(const void* p) {
    return (uint32_t)__cvta_generic_to_shared(p);
}
__device__ __forceinline__ void ldsm4(uint32_t& r0, uint32_t& r1, uint32_t& r2,
                                      uint32_t& r3, uint32_t a) {
    asm volatile("ldmatrix.sync.aligned.m8n8.x4.shared.b16 {%0,%1,%2,%3}, [%4];"
                 : "=r"(r0), "=r"(r1), "=r"(r2), "=r"(r3) : "r"(a));
}
__device__ __forceinline__ void ldsm4t(uint32_t& r0, uint32_t& r1, uint32_t& r2,
                                       uint32_t& r3, uint32_t a) {
    asm volatile("ldmatrix.sync.aligned.m8n8.x4.trans.shared.b16 {%0,%1,%2,%3}, [%4];"
                 : "=r"(r0), "=r"(r1), "=r"(r2), "=r"(r3) : "r"(a));
}
__device__ __forceinline__ void mma_bf16(float* c, const uint32_t* a,
                                         uint32_t b0, uint32_t b1) {
    asm volatile("mma.sync.aligned.m16n8k16.row.col.f32.bf16.bf16.f32 "
                 "{%0,%1,%2,%3}, {%4,%5,%6,%7}, {%8,%9}, {%0,%1,%2,%3};"
                 : "+f"(c[0]), "+f"(c[1]), "+f"(c[2]), "+f"(c[3])
                 : "r"(a[0]), "r"(a[1]), "r"(a[2]), "r"(a[3]), "r"(b0), "r"(b1));
}
__device__ __forceinline__ uint32_t packbf(__nv_bfloat16 a, __nv_bfloat16 b) {
    return (uint32_t)__bfloat16_as_ushort(a) | ((uint32_t)__bfloat16_as_ushort(b) << 16);
}
__device__ __forceinline__ void cvt_split(float4 v, uint2& hi, uint2& lo) {
    __nv_bfloat16 hx = __float2bfloat16(v.x), hy = __float2bfloat16(v.y);
    __nv_bfloat16 hz = __float2bfloat16(v.z), hw = __float2bfloat16(v.w);
    __nv_bfloat16 lx = __float2bfloat16(v.x - __bfloat162float(hx));
    __nv_bfloat16 ly = __float2bfloat16(v.y - __bfloat162float(hy));
    __nv_bfloat16 lz = __float2bfloat16(v.z - __bfloat162float(hz));
    __nv_bfloat16 lw = __float2bfloat16(v.w - __bfloat162float(hw));
    hi.x = packbf(hx, hy); hi.y = packbf(hz, hw);
    lo.x = packbf(lx, ly); lo.y = packbf(lz, lw);
}

// ---------------- K1: f_a = sigmoid(x . W_A + b_A) -> g_faT[i][b] ---------
__global__ __launch_bounds__(256) void k_fa(const float* __restrict__ x,
                                            const float* __restrict__ WA,
                                            const float* __restrict__ bA) {
    const int row = blockIdx.x * 8 + (threadIdx.x >> 5);
    const int lane = threadIdx.x & 31;
    const float4* xr = reinterpret_cast<const float4*>(x) + (size_t)row * (DIN / 4);
    const float4* w4 = reinterpret_cast<const float4*>(WA);
    float s = 0.f;
#pragma unroll
    for (int q = 0; q < 8; q++) {
        float4 xv = xr[lane + q * 32], wv = w4[lane + q * 32];
        s += xv.x * wv.x + xv.y * wv.y + xv.z * wv.z + xv.w * wv.w;
    }
#pragma unroll
    for (int o = 16; o; o >>= 1) s += __shfl_xor_sync(0xffffffffu, s, o);
    if (lane == 0) {
        const int b = row >> 10, i = row & (NI - 1);
        float tot = s + bA[0];
        g_faT[i * BB + b] = 1.f / (1.f + __expf(-tot));
    }
}

// ---------------- K2: phi0 transposed [j][i][b] ---------------------------
__global__ __launch_bounds__(256) void k_phi0(const float* __restrict__ bu,
                                              const float* __restrict__ bn) {
    const int p = blockIdx.x * 256 + threadIdx.x;
    const int j = p >> 10, i = p & (NI - 1);
    const float cu = bu[i * NOUT + j] * (1.0f / 64.0f) - bn[i * NOUT + j] * (63.0f / 64.0f);
    const float4* fa = reinterpret_cast<const float4*>(&g_faT[i * BB]);
    float4* dst = reinterpret_cast<float4*>(&g_phiT[((size_t)j * NI + i) * BB]);
#pragma unroll
    for (int q = 0; q < 8; q++) {
        float4 v = fa[q];
        dst[q] = make_float4(v.x * cu, v.y * cu, v.z * cu, v.w * cu);
    }
}

// ---------------- K3 (TENSOR): out[b,j,h] = sum_i phiT[j,i,b]*Wm[i,j,h] ---
// Grid (hb 0..3, j 0..63), 128 thr. Tile 32b x 256h, stage K=16.
// Warp tile 32b x 64h: 12 ldsm4 per 48 MMAs (wf/MMA = 1.0).
#define AMP 40
#define BNP2 264
template <int MODE>
__global__ __launch_bounds__(128) void k_mem(const float* __restrict__ Wm,
                                             float* __restrict__ outp) {
    const int j = blockIdx.y, hb = blockIdx.x;
    __shared__ __align__(16) uint16_t Ah[2][16][AMP], Al[2][16][AMP];
    __shared__ __align__(16) uint16_t Bh[2][16][BNP2], Bl[2][16][BNP2];
    const int tid = threadIdx.x, lane = tid & 31, w = tid >> 5;
    const int g = lane >> 3, r = lane & 7;
    const int fbr = tid >> 3, fbn = tid & 7;        // B: 16 rows, 8 f4 each thread
    const int far_ = tid >> 3, fac = (tid & 7) * 4; // A: 16 rows, 1 f4
    const float* WmB = Wm + (size_t)j * DOUT + (size_t)hb * 256;
    const float* Ab = g_phiT + (size_t)j * (NI * BB);

    float c[2][8][4];
#pragma unroll
    for (int mt = 0; mt < 2; mt++)
#pragma unroll
        for (int nt = 0; nt < 8; nt++)
#pragma unroll
            for (int e = 0; e < 4; e++) c[mt][nt][e] = 0.f;

    float4 bR[8], aR;
    {
        const float* br = WmB + (size_t)fbr * (NOUT * DOUT);
#pragma unroll
        for (int q = 0; q < 8; q++)
            bR[q] = *reinterpret_cast<const float4*>(br + (size_t)(fbn + q * 8) * 4);
        aR = *reinterpret_cast<const float4*>(Ab + (size_t)far_ * BB + fac);
    }
    {
#pragma unroll
        for (int q = 0; q < 8; q++) {
            uint2 hi, lo; cvt_split(bR[q], hi, lo);
            const int n = (fbn + q * 8) * 4;
            *reinterpret_cast<uint2*>(&Bh[0][fbr][n]) = hi;
            *reinterpret_cast<uint2*>(&Bl[0][fbr][n]) = lo;
        }
        uint2 hi, lo; cvt_split(aR, hi, lo);
        *reinterpret_cast<uint2*>(&Ah[0][far_][fac]) = hi;
        *reinterpret_cast<uint2*>(&Al[0][far_][fac]) = lo;
    }
    __syncthreads();

    const int NSTG = NI / 16;  // 64
    for (int t = 0; t < NSTG; t++) {
        const int cur = t & 1;
        const bool more = (t + 1 < NSTG);
        if (more) {
            const int i0 = (t + 1) * 16;
            const float* br = WmB + (size_t)(i0 + fbr) * (NOUT * DOUT);
#pragma unroll
            for (int q = 0; q < 8; q++)
                bR[q] = *reinterpret_cast<const float4*>(br + (size_t)(fbn + q * 8) * 4);
            aR = *reinterpret_cast<const float4*>(Ab + (size_t)(i0 + far_) * BB + fac);
        }
        {
            uint32_t ah[2][4], al[2][4], bh[8][2], bl[8][2];
#pragma unroll
            for (int mt = 0; mt < 2; mt++) {
                const int ak = (g >> 1) * 8 + r, am = mt * 16 + (g & 1) * 8;
                ldsm4t(ah[mt][0], ah[mt][1], ah[mt][2], ah[mt][3],
                       smem_u32(&Ah[cur][ak][am]));
                ldsm4t(al[mt][0], al[mt][1], al[mt][2], al[mt][3],
                       smem_u32(&Al[cur][ak][am]));
            }
#pragma unroll
            for (int p = 0; p < 4; p++) {
                const int bk = (g & 1) * 8 + r;
                const int bn = w * 64 + p * 16 + (g >> 1) * 8;
                ldsm4t(bh[2 * p][0], bh[2 * p][1], bh[2 * p + 1][0], bh[2 * p + 1][1],
                       smem_u32(&Bh[cur][bk][bn]));
                ldsm4t(bl[2 * p][0], bl[2 * p][1], bl[2 * p + 1][0], bl[2 * p + 1][1],
                       smem_u32(&Bl[cur][bk][bn]));
            }
#pragma unroll
            for (int mt = 0; mt < 2; mt++)
#pragma unroll
                for (int nt = 0; nt < 8; nt++) {
                    mma_bf16(c[mt][nt], ah[mt], bh[nt][0], bh[nt][1]);
                    mma_bf16(c[mt][nt], ah[mt], bl[nt][0], bl[nt][1]);
                    mma_bf16(c[mt][nt], al[mt], bh[nt][0], bh[nt][1]);
                }
        }
        if (more) {
            const int nxt = 1 - cur;
#pragma unroll
            for (int q = 0; q < 8; q++) {
                uint2 hi, lo; cvt_split(bR[q], hi, lo);
                const int n = (fbn + q * 8) * 4;
                *reinterpret_cast<uint2*>(&Bh[nxt][fbr][n]) = hi;
                *reinterpret_cast<uint2*>(&Bl[nxt][fbr][n]) = lo;
            }
            uint2 hi, lo; cvt_split(aR, hi, lo);
            *reinterpret_cast<uint2*>(&Ah[nxt][far_][fac]) = hi;
            *reinterpret_cast<uint2*>(&Al[nxt][far_][fac]) = lo;
        }
        __syncthreads();
    }

    float* dst = (MODE == 0) ? g_xout0 : outp;
#pragma unroll
    for (int mt = 0; mt < 2; mt++)
#pragma unroll
        for (int nt = 0; nt < 8; nt++) {
            const int m0 = mt * 16 + (lane >> 2);
            const int n = hb * 256 + w * 64 + nt * 8 + (lane & 3) * 2;
            float* o0 = dst + ((size_t)(m0 * NOUT + j)) * DOUT + n;
            *reinterpret_cast<float2*>(o0) = make_float2(c[mt][nt][0], c[mt][nt][1]);
            float* o1 = dst + ((size_t)((m0 + 8) * NOUT + j)) * DOUT + n;
            *reinterpret_cast<float2*>(o1) = make_float2(c[mt][nt][2], c[mt][nt][3]);
        }
}

// ---------------- K4 (TENSOR, split-K): pred partials ---------------------
#define PKP 24
#define BNP 136
__global__ __launch_bounds__(128) void k_predp(const float* __restrict__ WG) {
    const int nb = blockIdx.x, mb = blockIdx.y, ks = blockIdx.z;
    const int mBase = mb * 64, nBase = nb * 128, kBase = ks * 256;
    __shared__ __align__(16) uint16_t Ah[2][64][PKP], Al[2][64][PKP];
    __shared__ __align__(16) uint16_t Bh[2][16][BNP], Bl[2][16][BNP];
    const int tid = threadIdx.x, lane = tid & 31, w = tid >> 5;
    const int g = lane >> 3, r = lane & 7;
    const int fam = tid & 63, fak = (tid >> 6) * 8;
    const int fbr = tid >> 3, fbn = tid & 7;
    const int arow = lane & 15, acol = (lane >> 4) * 8;

    float c[4][4][4];
#pragma unroll
    for (int mt = 0; mt < 4; mt++)
#pragma unroll
        for (int nt = 0; nt < 4; nt++)
#pragma unroll
            for (int e = 0; e < 4; e++) c[mt][nt][e] = 0.f;

    float4 aR[2], bR[4];
#pragma unroll
    for (int q = 0; q < 2; q++)
        aR[q] = *reinterpret_cast<const float4*>(g_xout0 + (size_t)(mBase + fam) * DOUT + kBase + fak + q * 4);
#pragma unroll
    for (int q = 0; q < 4; q++)
        bR[q] = *reinterpret_cast<const float4*>(WG + (size_t)(kBase + fbr) * DIN + nBase + (size_t)(fbn + q * 8) * 4);
    {
#pragma unroll
        for (int q = 0; q < 2; q++) {
            uint2 hi, lo; cvt_split(aR[q], hi, lo);
            *reinterpret_cast<uint2*>(&Ah[0][fam][fak + q * 4]) = hi;
            *reinterpret_cast<uint2*>(&Al[0][fam][fak + q * 4]) = lo;
        }
#pragma unroll
        for (int q = 0; q < 4; q++) {
            uint2 hi, lo; cvt_split(bR[q], hi, lo);
            const int n = (fbn + q * 8) * 4;
            *reinterpret_cast<uint2*>(&Bh[0][fbr][n]) = hi;
            *reinterpret_cast<uint2*>(&Bl[0][fbr][n]) = lo;
        }
    }
    __syncthreads();

    const int NSTG = 256 / 16;  // 16
    for (int t = 0; t < NSTG; t++) {
        const int cur = t & 1;
        const bool more = (t + 1 < NSTG);
        if (more) {
            const int k0 = kBase + (t + 1) * 16;
#pragma unroll
            for (int q = 0; q < 2; q++)
                aR[q] = *reinterpret_cast<const float4*>(g_xout0 + (size_t)(mBase + fam) * DOUT + k0 + fak + q * 4);
#pragma unroll
            for (int q = 0; q < 4; q++)
                bR[q] = *reinterpret_cast<const float4*>(WG + (size_t)(k0 + fbr) * DIN + nBase + (size_t)(fbn + q * 8) * 4);
        }
        {
            uint32_t ah[4][4], al[4][4], bh[4][2], bl[4][2];
#pragma unroll
            for (int mt = 0; mt < 4; mt++) {
                ldsm4(ah[mt][0], ah[mt][1], ah[mt][2], ah[mt][3],
                      smem_u32(&Ah[cur][mt * 16 + arow][acol]));
                ldsm4(al[mt][0], al[mt][1], al[mt][2], al[mt][3],
                      smem_u32(&Al[cur][mt * 16 + arow][acol]));
            }
#pragma unroll
            for (int p = 0; p < 2; p++) {
                const int bk = (g & 1) * 8 + r;
                const int bn = w * 32 + p * 16 + (g >> 1) * 8;
                ldsm4t(bh[2 * p][0], bh[2 * p][1], bh[2 * p + 1][0], bh[2 * p + 1][1],
                       smem_u32(&Bh[cur][bk][bn]));
                ldsm4t(bl[2 * p][0], bl[2 * p][1], bl[2 * p + 1][0], bl[2 * p + 1][1],
                       smem_u32(&Bl[cur][bk][bn]));
            }
#pragma unroll
            for (int mt = 0; mt < 4; mt++)
#pragma unroll
                for (int nt = 0; nt < 4; nt++) {
                    mma_bf16(c[mt][nt], ah[mt], bh[nt][0], bh[nt][1]);
                    mma_bf16(c[mt][nt], ah[mt], bl[nt][0], bl[nt][1]);
                    mma_bf16(c[mt][nt], al[mt], bh[nt][0], bh[nt][1]);
                }
        }
        if (more) {
            const int nxt = 1 - cur;
#pragma unroll
            for (int q = 0; q < 2; q++) {
                uint2 hi, lo; cvt_split(aR[q], hi, lo);
                *reinterpret_cast<uint2*>(&Ah[nxt][fam][fak + q * 4]) = hi;
                *reinterpret_cast<uint2*>(&Al[nxt][fam][fak + q * 4]) = lo;
            }
#pragma unroll
            for (int q = 0; q < 4; q++) {
                uint2 hi, lo; cvt_split(bR[q], hi, lo);
                const int n = (fbn + q * 8) * 4;
                *reinterpret_cast<uint2*>(&Bh[nxt][fbr][n]) = hi;
                *reinterpret_cast<uint2*>(&Bl[nxt][fbr][n]) = lo;
            }
        }
        __syncthreads();
    }

    float* dst = g_ppart[ks];
#pragma unroll
    for (int nt = 0; nt < 4; nt++) {
        const int n = nBase + w * 32 + nt * 8 + (lane & 3) * 2;
#pragma unroll
        for (int mt = 0; mt < 4; mt++) {
            const int m0 = mBase + mt * 16 + (lane >> 2);
            *reinterpret_cast<float2*>(dst + (size_t)m0 * DIN + n) =
                make_float2(c[mt][nt][0], c[mt][nt][1]);
            *reinterpret_cast<float2*>(dst + (size_t)(m0 + 8) * DIN + n) =
                make_float2(c[mt][nt][2], c[mt][nt][3]);
        }
    }
}

// ---------------- K4b: combine partials + bias -> g_pred ------------------
__global__ __launch_bounds__(256) void k_comb(const float* __restrict__ bG) {
    const int idx = blockIdx.x * 256 + threadIdx.x;
    const int S = BB * NOUT * DIN / 4;
    const float4* p = reinterpret_cast<const float4*>(g_ppart);
    float4 a = p[idx], b2 = p[idx + S], c2 = p[idx + 2 * S], d = p[idx + 3 * S];
    const float4 bg = reinterpret_cast<const float4*>(bG)[idx & (DIN / 4 - 1)];
    reinterpret_cast<float4*>(g_pred)[idx] = make_float4(
        a.x + b2.x + c2.x + d.x + bg.x, a.y + b2.y + c2.y + d.y + bg.y,
        a.z + b2.z + c2.z + d.z + bg.z, a.w + b2.w + c2.w + d.w + bg.w);
}

// ---------------- K5 (TENSOR, round-7 shape): S -> softmax -> phi1 --------
// Grid (it 0..7, b 0..31), 128 thr. Tile 128i x 64j, stage K=16.
__global__ __launch_bounds__(128) void k_sim(const float* __restrict__ x,
                                             const float* __restrict__ bu,
                                             const float* __restrict__ bn) {
    const int i0 = blockIdx.x * 128;
    const int b = blockIdx.y;
    __shared__ __align__(16) uint16_t Ah[2][128][PKP], Al[2][128][PKP];
    __shared__ __align__(16) uint16_t Bh[2][NOUT][PKP], Bl[2][NOUT][PKP];
    const int tid = threadIdx.x, lane = tid & 31, w = tid >> 5;
    const int fbj = tid & 63, fbk = (tid >> 6) * 8;
    const int arow = lane & 15, acol = (lane >> 4) * 8;
    const int brow = ((lane >> 4) & 1) * 8 + (lane & 7), bcol = ((lane >> 3) & 1) * 8;

    const float* Arow = x + ((size_t)b * NI + i0 + tid) * DIN;
    const float* Brow = g_pred + ((size_t)b * NOUT + fbj) * DIN;

    float c[2][8][4];
#pragma unroll
    for (int mt = 0; mt < 2; mt++)
#pragma unroll
        for (int nt = 0; nt < 8; nt++)
#pragma unroll
            for (int e = 0; e < 4; e++) c[mt][nt][e] = 0.f;

    float4 aR[4]; float4 bR[2];
#pragma unroll
    for (int q = 0; q < 4; q++)
        aR[q] = *reinterpret_cast<const float4*>(Arow + q * 4);
#pragma unroll
    for (int q = 0; q < 2; q++)
        bR[q] = *reinterpret_cast<const float4*>(Brow + fbk + q * 4);
    {
#pragma unroll
        for (int q = 0; q < 4; q++) {
            uint2 hi, lo; cvt_split(aR[q], hi, lo);
            *reinterpret_cast<uint2*>(&Ah[0][tid][q * 4]) = hi;
            *reinterpret_cast<uint2*>(&Al[0][tid][q * 4]) = lo;
        }
#pragma unroll
        for (int q = 0; q < 2; q++) {
            uint2 hi, lo; cvt_split(bR[q], hi, lo);
            *reinterpret_cast<uint2*>(&Bh[0][fbj][fbk + q * 4]) = hi;
            *reinterpret_cast<uint2*>(&Bl[0][fbj][fbk + q * 4]) = lo;
        }
    }
    __syncthreads();

    const int NSTG = DIN / 16;  // 64
    for (int t = 0; t < NSTG; t++) {
        const int cur = t & 1;
        const bool more = (t + 1 < NSTG);
        if (more) {
            const int d0 = (t + 1) * 16;
#pragma unroll
            for (int q = 0; q < 4; q++)
                aR[q] = *reinterpret_cast<const float4*>(Arow + d0 + q * 4);
#pragma unroll
            for (int q = 0; q < 2; q++)
                bR[q] = *reinterpret_cast<const float4*>(Brow + d0 + fbk + q * 4);
        }
        {
            uint32_t ah[2][4], al[2][4], bh[8][2], bl[8][2];
#pragma unroll
            for (int mt = 0; mt < 2; mt++) {
                const int am = w * 32 + mt * 16 + arow;
                ldsm4(ah[mt][0], ah[mt][1], ah[mt][2], ah[mt][3],
                      smem_u32(&Ah[cur][am][acol]));
                ldsm4(al[mt][0], al[mt][1], al[mt][2], al[mt][3],
                      smem_u32(&Al[cur][am][acol]));
            }
#pragma unroll
            for (int p = 0; p < 4; p++) {
                const int bj = p * 16 + brow;
                ldsm4(bh[2 * p][0], bh[2 * p][1], bh[2 * p + 1][0], bh[2 * p + 1][1],
                      smem_u32(&Bh[cur][bj][bcol]));
                ldsm4(bl[2 * p][0], bl[2 * p][1], bl[2 * p + 1][0], bl[2 * p + 1][1],
                      smem_u32(&Bl[cur][bj][bcol]));
            }
#pragma unroll
            for (int mt = 0; mt < 2; mt++)
#pragma unroll
                for (int nt = 0; nt < 8; nt++) {
                    mma_bf16(c[mt][nt], ah[mt], bh[nt][0], bh[nt][1]);
                    mma_bf16(c[mt][nt], ah[mt], bl[nt][0], bl[nt][1]);
                    mma_bf16(c[mt][nt], al[mt], bh[nt][0], bh[nt][1]);
                }
        }
        if (more) {
            const int nxt = 1 - cur;
#pragma unroll
            for (int q = 0; q < 4; q++) {
                uint2 hi, lo; cvt_split(aR[q], hi, lo);
                *reinterpret_cast<uint2*>(&Ah[nxt][tid][q * 4]) = hi;
                *reinterpret_cast<uint2*>(&Al[nxt][tid][q * 4]) = lo;
            }
#pragma unroll
            for (int q = 0; q < 2; q++) {
                uint2 hi, lo; cvt_split(bR[q], hi, lo);
                *reinterpret_cast<uint2*>(&Bh[nxt][fbj][fbk + q * 4]) = hi;
                *reinterpret_cast<uint2*>(&Bl[nxt][fbj][fbk + q * 4]) = lo;
            }
        }
        __syncthreads();
    }

    const float scale = 0.03125f;  // 1024^-0.5
#pragma unroll
    for (int mt = 0; mt < 2; mt++) {
#pragma unroll
        for (int half = 0; half < 2; half++) {
            const int rg = i0 + w * 32 + mt * 16 + (lane >> 2) + half * 8;
            float v[16];
#pragma unroll
            for (int nt = 0; nt < 8; nt++) {
                v[nt * 2 + 0] = c[mt][nt][half * 2 + 0] * scale;
                v[nt * 2 + 1] = c[mt][nt][half * 2 + 1] * scale;
            }
            float mx = v[0];
#pragma unroll
            for (int q = 1; q < 16; q++) mx = fmaxf(mx, v[q]);
            mx = fmaxf(mx, __shfl_xor_sync(0xffffffffu, mx, 1));
            mx = fmaxf(mx, __shfl_xor_sync(0xffffffffu, mx, 2));
            float e[16], s = 0.f;
#pragma unroll
            for (int q = 0; q < 16; q++) { e[q] = __expf(v[q] - mx); s += e[q]; }
            s += __shfl_xor_sync(0xffffffffu, s, 1);
            s += __shfl_xor_sync(0xffffffffu, s, 2);
            const float inv = 1.f / s;
            const float fa = g_faT[rg * BB + b];
            float* o = g_phi1 + ((size_t)b * NI + rg) * NOUT;
#pragma unroll
            for (int nt = 0; nt < 8; nt++) {
                const int jj = nt * 8 + (lane & 3) * 2;
                const float2 bu2 = *reinterpret_cast<const float2*>(bu + (size_t)rg * NOUT + jj);
                const float2 bn2 = *reinterpret_cast<const float2*>(bn + (size_t)rg * NOUT + jj);
                *reinterpret_cast<float2*>(o + jj) = make_float2(
                    fa * ((bu2.x + bn2.x) * e[nt * 2 + 0] * inv - bn2.x),
                    fa * ((bu2.y + bn2.y) * e[nt * 2 + 1] * inv - bn2.y));
            }
        }
    }
}

// ---------------- K6: transpose phi1 [b][i][j] -> phiT [j][i][b] ----------
__global__ __launch_bounds__(256) void k_tr() {
    const int i = blockIdx.x;
    __shared__ float t[32][65];
    const int tid = threadIdx.x;
#pragma unroll
    for (int q = 0; q < 8; q++) {
        int idx = tid + q * 256;
        int bb = idx >> 6, j = idx & 63;
        t[bb][j] = g_phi1[((size_t)bb * NI + i) * NOUT + j];
    }
    __syncthreads();
#pragma unroll
    for (int q = 0; q < 8; q++) {
        int idx = tid + q * 256;
        int j = idx >> 5, bb = idx & 31;
        g_phiT[((size_t)j * NI + i) * BB + bb] = t[bb][j];
    }
}

// ---------------- launch ---------------------------------------------------
extern "C" void kernel_launch(void* const* d_in, const int* in_sizes, int n_in,
                              void* d_out, int out_size) {
    const float* x  = (const float*)d_in[0];
    const float* WA = (const float*)d_in[1];
    const float* bA = (const float*)d_in[2];
    const float* Wm = (const float*)d_in[3];
    const float* WG = (const float*)d_in[4];
    const float* bG = (const float*)d_in[5];
    const float* bu = (const float*)d_in[6];
    const float* bn = (const float*)d_in[7];
    float* out = (float*)d_out;

    k_fa<<<4096, 256>>>(x, WA, bA);
    k_phi0<<<256, 256>>>(bu, bn);
    k_mem<0><<<dim3(4, 64), 128>>>(Wm, nullptr);
    k_predp<<<dim3(8, 32, 4), 128>>>(WG);
    k_comb<<<BB * NOUT * DIN / 1024, 256>>>(bG);
    k_sim<<<dim3(8, 32), 128>>>(x, bu, bn);
    k_tr<<<NI, 256>>>();
    k_mem<1><<<dim3(4, 64), 128>>>(Wm, out);
}

// round 10
// speedup vs baseline: 1.5639x; 1.5639x over previous
#include <cuda_runtime.h>
#include <cuda_bf16.h>
#include <cstdint>

#define BB 32
#define NI 1024
#define DIN 1024
#define NOUT 64
#define DOUT 1024

// ---------------- device scratch ----------------
__device__ float g_faT[NI * BB];              // f_a transposed [i][b]
__device__ float g_xout0[BB * NOUT * DOUT];   // iter-0 output [b][j][h]
__device__ float g_pred[BB * NOUT * DIN];     // pred [b][j][d]
__device__ float g_phi1[BB * NI * NOUT];      // phi iter-1 [b][i][j]
__device__ float g_phiT[NOUT * NI * BB];      // phi transposed [j][i][b]
__device__ float g_ppart[4][BB * NOUT * DIN]; // k_pred split-K partials

// ---------------- mma helpers ----------------
__device__ __forceinline__ uint32_t smem_u32(const void* p) {
    return (uint32_t)__cvta_generic_to_shared(p);
}
__device__ __forceinline__ void ldsm4(uint32_t& r0, uint32_t& r1, uint32_t& r2,
                                      uint32_t& r3, uint32_t a) {
    asm volatile("ldmatrix.sync.aligned.m8n8.x4.shared.b16 {%0,%1,%2,%3}, [%4];"
                 : "=r"(r0), "=r"(r1), "=r"(r2), "=r"(r3) : "r"(a));
}
__device__ __forceinline__ void ldsm4t(uint32_t& r0, uint32_t& r1, uint32_t& r2,
                                       uint32_t& r3, uint32_t a) {
    asm volatile("ldmatrix.sync.aligned.m8n8.x4.trans.shared.b16 {%0,%1,%2,%3}, [%4];"
                 : "=r"(r0), "=r"(r1), "=r"(r2), "=r"(r3) : "r"(a));
}
__device__ __forceinline__ void mma_bf16(float* c, const uint32_t* a,
                                         uint32_t b0, uint32_t b1) {
    asm volatile("mma.sync.aligned.m16n8k16.row.col.f32.bf16.bf16.f32 "
                 "{%0,%1,%2,%3}, {%4,%5,%6,%7}, {%8,%9}, {%0,%1,%2,%3};"
                 : "+f"(c[0]), "+f"(c[1]), "+f"(c[2]), "+f"(c[3])
                 : "r"(a[0]), "r"(a[1]), "r"(a[2]), "r"(a[3]), "r"(b0), "r"(b1));
}
__device__ __forceinline__ uint32_t packbf(__nv_bfloat16 a, __nv_bfloat16 b) {
    return (uint32_t)__bfloat16_as_ushort(a) | ((uint32_t)__bfloat16_as_ushort(b) << 16);
}
__device__ __forceinline__ void cvt_split(float4 v, uint2& hi, uint2& lo) {
    __nv_bfloat16 hx = __float2bfloat16(v.x), hy = __float2bfloat16(v.y);
    __nv_bfloat16 hz = __float2bfloat16(v.z), hw = __float2bfloat16(v.w);
    __nv_bfloat16 lx = __float2bfloat16(v.x - __bfloat162float(hx));
    __nv_bfloat16 ly = __float2bfloat16(v.y - __bfloat162float(hy));
    __nv_bfloat16 lz = __float2bfloat16(v.z - __bfloat162float(hz));
    __nv_bfloat16 lw = __float2bfloat16(v.w - __bfloat162float(hw));
    hi.x = packbf(hx, hy); hi.y = packbf(hz, hw);
    lo.x = packbf(lx, ly); lo.y = packbf(lz, lw);
}

// ---------------- K1: f_a = sigmoid(x . W_A + b_A) -> g_faT[i][b] ---------
__global__ __launch_bounds__(256) void k_fa(const float* __restrict__ x,
                                            const float* __restrict__ WA,
                                            const float* __restrict__ bA) {
    const int row = blockIdx.x * 8 + (threadIdx.x >> 5);
    const int lane = threadIdx.x & 31;
    const float4* xr = reinterpret_cast<const float4*>(x) + (size_t)row * (DIN / 4);
    const float4* w4 = reinterpret_cast<const float4*>(WA);
    float s = 0.f;
#pragma unroll
    for (int q = 0; q < 8; q++) {
        float4 xv = xr[lane + q * 32], wv = w4[lane + q * 32];
        s += xv.x * wv.x + xv.y * wv.y + xv.z * wv.z + xv.w * wv.w;
    }
#pragma unroll
    for (int o = 16; o; o >>= 1) s += __shfl_xor_sync(0xffffffffu, s, o);
    if (lane == 0) {
        const int b = row >> 10, i = row & (NI - 1);
        float tot = s + bA[0];
        g_faT[i * BB + b] = 1.f / (1.f + __expf(-tot));
    }
}

// ---------------- K2: phi0 transposed [j][i][b] ---------------------------
__global__ __launch_bounds__(256) void k_phi0(const float* __restrict__ bu,
                                              const float* __restrict__ bn) {
    const int p = blockIdx.x * 256 + threadIdx.x;
    const int j = p >> 10, i = p & (NI - 1);
    const float cu = bu[i * NOUT + j] * (1.0f / 64.0f) - bn[i * NOUT + j] * (63.0f / 64.0f);
    const float4* fa = reinterpret_cast<const float4*>(&g_faT[i * BB]);
    float4* dst = reinterpret_cast<float4*>(&g_phiT[((size_t)j * NI + i) * BB]);
#pragma unroll
    for (int q = 0; q < 8; q++) {
        float4 v = fa[q];
        dst[q] = make_float4(v.x * cu, v.y * cu, v.z * cu, v.w * cu);
    }
}

// ---------------- K3 (TENSOR, round-7 proven): out = phiT . Wm ------------
// Grid (hb 0..7, j 0..63), 128 thr. Tile 32b x 128h, stage K=32.
#define AMP 40
#define BNP 136
template <int MODE>
__global__ __launch_bounds__(128) void k_mem(const float* __restrict__ Wm,
                                             float* __restrict__ outp) {
    const int j = blockIdx.y, hb = blockIdx.x;
    __shared__ __align__(16) uint16_t Ah[2][32][AMP], Al[2][32][AMP];
    __shared__ __align__(16) uint16_t Bh[2][32][BNP], Bl[2][32][BNP];
    const int tid = threadIdx.x, lane = tid & 31, w = tid >> 5;
    const int fr = tid >> 2, fq = tid & 3;
    const int g = lane >> 3, r = lane & 7;
    const float* WmB = Wm + (size_t)j * DOUT + (size_t)hb * 128;
    const float* Ab = g_phiT + (size_t)j * (NI * BB);

    float c[2][4][4];
#pragma unroll
    for (int mt = 0; mt < 2; mt++)
#pragma unroll
        for (int nt = 0; nt < 4; nt++)
#pragma unroll
            for (int e = 0; e < 4; e++) c[mt][nt][e] = 0.f;

    float4 bR[8], aR[2];
    {
        const float* br = WmB + (size_t)fr * (NOUT * DOUT);
#pragma unroll
        for (int q = 0; q < 8; q++)
            bR[q] = *reinterpret_cast<const float4*>(br + (size_t)(fq + q * 4) * 4);
        const float* ar = Ab + (size_t)fr * BB + fq * 8;
        aR[0] = *reinterpret_cast<const float4*>(ar);
        aR[1] = *reinterpret_cast<const float4*>(ar + 4);
    }
    {
#pragma unroll
        for (int q = 0; q < 8; q++) {
            uint2 hi, lo; cvt_split(bR[q], hi, lo);
            const int n = (fq + q * 4) * 4;
            *reinterpret_cast<uint2*>(&Bh[0][fr][n]) = hi;
            *reinterpret_cast<uint2*>(&Bl[0][fr][n]) = lo;
        }
        uint2 h0, l0, h1, l1;
        cvt_split(aR[0], h0, l0); cvt_split(aR[1], h1, l1);
        const int m = fq * 8;
        *reinterpret_cast<uint4*>(&Ah[0][fr][m]) = make_uint4(h0.x, h0.y, h1.x, h1.y);
        *reinterpret_cast<uint4*>(&Al[0][fr][m]) = make_uint4(l0.x, l0.y, l1.x, l1.y);
    }
    __syncthreads();

    const int NSTG = NI / 32;
    for (int t = 0; t < NSTG; t++) {
        const int cur = t & 1;
        const bool more = (t + 1 < NSTG);
        if (more) {
            const int i0 = (t + 1) * 32;
            const float* br = WmB + (size_t)(i0 + fr) * (NOUT * DOUT);
#pragma unroll
            for (int q = 0; q < 8; q++)
                bR[q] = *reinterpret_cast<const float4*>(br + (size_t)(fq + q * 4) * 4);
            const float* ar = Ab + (size_t)(i0 + fr) * BB + fq * 8;
            aR[0] = *reinterpret_cast<const float4*>(ar);
            aR[1] = *reinterpret_cast<const float4*>(ar + 4);
        }
#pragma unroll
        for (int kk = 0; kk < 32; kk += 16) {
            uint32_t ah[2][4], al[2][4], bh[4][2], bl[4][2];
#pragma unroll
            for (int mt = 0; mt < 2; mt++) {
                const int ak = kk + (g >> 1) * 8 + r, am = mt * 16 + (g & 1) * 8;
                ldsm4t(ah[mt][0], ah[mt][1], ah[mt][2], ah[mt][3],
                       smem_u32(&Ah[cur][ak][am]));
                ldsm4t(al[mt][0], al[mt][1], al[mt][2], al[mt][3],
                       smem_u32(&Al[cur][ak][am]));
            }
#pragma unroll
            for (int p = 0; p < 2; p++) {
                const int bk = kk + (g & 1) * 8 + r;
                const int bn = w * 32 + p * 16 + (g >> 1) * 8;
                ldsm4t(bh[2 * p][0], bh[2 * p][1], bh[2 * p + 1][0], bh[2 * p + 1][1],
                       smem_u32(&Bh[cur][bk][bn]));
                ldsm4t(bl[2 * p][0], bl[2 * p][1], bl[2 * p + 1][0], bl[2 * p + 1][1],
                       smem_u32(&Bl[cur][bk][bn]));
            }
#pragma unroll
            for (int mt = 0; mt < 2; mt++)
#pragma unroll
                for (int nt = 0; nt < 4; nt++) {
                    mma_bf16(c[mt][nt], ah[mt], bh[nt][0], bh[nt][1]);
                    mma_bf16(c[mt][nt], ah[mt], bl[nt][0], bl[nt][1]);
                    mma_bf16(c[mt][nt], al[mt], bh[nt][0], bh[nt][1]);
                }
        }
        if (more) {
            const int nxt = 1 - cur;
#pragma unroll
            for (int q = 0; q < 8; q++) {
                uint2 hi, lo; cvt_split(bR[q], hi, lo);
                const int n = (fq + q * 4) * 4;
                *reinterpret_cast<uint2*>(&Bh[nxt][fr][n]) = hi;
                *reinterpret_cast<uint2*>(&Bl[nxt][fr][n]) = lo;
            }
            uint2 h0, l0, h1, l1;
            cvt_split(aR[0], h0, l0); cvt_split(aR[1], h1, l1);
            const int m = fq * 8;
            *reinterpret_cast<uint4*>(&Ah[nxt][fr][m]) = make_uint4(h0.x, h0.y, h1.x, h1.y);
            *reinterpret_cast<uint4*>(&Al[nxt][fr][m]) = make_uint4(l0.x, l0.y, l1.x, l1.y);
        }
        __syncthreads();
    }

    float* dst = (MODE == 0) ? g_xout0 : outp;
#pragma unroll
    for (int mt = 0; mt < 2; mt++)
#pragma unroll
        for (int nt = 0; nt < 4; nt++) {
            const int m0 = mt * 16 + (lane >> 2);
            const int n = hb * 128 + w * 32 + nt * 8 + (lane & 3) * 2;
            float* o0 = dst + ((size_t)(m0 * NOUT + j)) * DOUT + n;
            *reinterpret_cast<float2*>(o0) = make_float2(c[mt][nt][0], c[mt][nt][1]);
            float* o1 = dst + ((size_t)((m0 + 8) * NOUT + j)) * DOUT + n;
            *reinterpret_cast<float2*>(o1) = make_float2(c[mt][nt][2], c[mt][nt][3]);
        }
}

// ---------------- K4 (TENSOR, split-K): pred partials ---------------------
#define PKP 24
__global__ __launch_bounds__(128) void k_predp(const float* __restrict__ WG) {
    const int nb = blockIdx.x, mb = blockIdx.y, ks = blockIdx.z;
    const int mBase = mb * 64, nBase = nb * 128, kBase = ks * 256;
    __shared__ __align__(16) uint16_t Ah[2][64][PKP], Al[2][64][PKP];
    __shared__ __align__(16) uint16_t Bh[2][16][BNP], Bl[2][16][BNP];
    const int tid = threadIdx.x, lane = tid & 31, w = tid >> 5;
    const int g = lane >> 3, r = lane & 7;
    const int fam = tid & 63, fak = (tid >> 6) * 8;
    const int fbr = tid >> 3, fbn = tid & 7;
    const int arow = lane & 15, acol = (lane >> 4) * 8;

    float c[4][4][4];
#pragma unroll
    for (int mt = 0; mt < 4; mt++)
#pragma unroll
        for (int nt = 0; nt < 4; nt++)
#pragma unroll
            for (int e = 0; e < 4; e++) c[mt][nt][e] = 0.f;

    float4 aR[2], bR[4];
#pragma unroll
    for (int q = 0; q < 2; q++)
        aR[q] = *reinterpret_cast<const float4*>(g_xout0 + (size_t)(mBase + fam) * DOUT + kBase + fak + q * 4);
#pragma unroll
    for (int q = 0; q < 4; q++)
        bR[q] = *reinterpret_cast<const float4*>(WG + (size_t)(kBase + fbr) * DIN + nBase + (size_t)(fbn + q * 8) * 4);
    {
#pragma unroll
        for (int q = 0; q < 2; q++) {
            uint2 hi, lo; cvt_split(aR[q], hi, lo);
            *reinterpret_cast<uint2*>(&Ah[0][fam][fak + q * 4]) = hi;
            *reinterpret_cast<uint2*>(&Al[0][fam][fak + q * 4]) = lo;
        }
#pragma unroll
        for (int q = 0; q < 4; q++) {
            uint2 hi, lo; cvt_split(bR[q], hi, lo);
            const int n = (fbn + q * 8) * 4;
            *reinterpret_cast<uint2*>(&Bh[0][fbr][n]) = hi;
            *reinterpret_cast<uint2*>(&Bl[0][fbr][n]) = lo;
        }
    }
    __syncthreads();

    const int NSTG = 256 / 16;
    for (int t = 0; t < NSTG; t++) {
        const int cur = t & 1;
        const bool more = (t + 1 < NSTG);
        if (more) {
            const int k0 = kBase + (t + 1) * 16;
#pragma unroll
            for (int q = 0; q < 2; q++)
                aR[q] = *reinterpret_cast<const float4*>(g_xout0 + (size_t)(mBase + fam) * DOUT + k0 + fak + q * 4);
#pragma unroll
            for (int q = 0; q < 4; q++)
                bR[q] = *reinterpret_cast<const float4*>(WG + (size_t)(k0 + fbr) * DIN + nBase + (size_t)(fbn + q * 8) * 4);
        }
        {
            uint32_t ah[4][4], al[4][4], bh[4][2], bl[4][2];
#pragma unroll
            for (int mt = 0; mt < 4; mt++) {
                ldsm4(ah[mt][0], ah[mt][1], ah[mt][2], ah[mt][3],
                      smem_u32(&Ah[cur][mt * 16 + arow][acol]));
                ldsm4(al[mt][0], al[mt][1], al[mt][2], al[mt][3],
                      smem_u32(&Al[cur][mt * 16 + arow][acol]));
            }
#pragma unroll
            for (int p = 0; p < 2; p++) {
                const int bk = (g & 1) * 8 + r;
                const int bn = w * 32 + p * 16 + (g >> 1) * 8;
                ldsm4t(bh[2 * p][0], bh[2 * p][1], bh[2 * p + 1][0], bh[2 * p + 1][1],
                       smem_u32(&Bh[cur][bk][bn]));
                ldsm4t(bl[2 * p][0], bl[2 * p][1], bl[2 * p + 1][0], bl[2 * p + 1][1],
                       smem_u32(&Bl[cur][bk][bn]));
            }
#pragma unroll
            for (int mt = 0; mt < 4; mt++)
#pragma unroll
                for (int nt = 0; nt < 4; nt++) {
                    mma_bf16(c[mt][nt], ah[mt], bh[nt][0], bh[nt][1]);
                    mma_bf16(c[mt][nt], ah[mt], bl[nt][0], bl[nt][1]);
                    mma_bf16(c[mt][nt], al[mt], bh[nt][0], bh[nt][1]);
                }
        }
        if (more) {
            const int nxt = 1 - cur;
#pragma unroll
            for (int q = 0; q < 2; q++) {
                uint2 hi, lo; cvt_split(aR[q], hi, lo);
                *reinterpret_cast<uint2*>(&Ah[nxt][fam][fak + q * 4]) = hi;
                *reinterpret_cast<uint2*>(&Al[nxt][fam][fak + q * 4]) = lo;
            }
#pragma unroll
            for (int q = 0; q < 4; q++) {
                uint2 hi, lo; cvt_split(bR[q], hi, lo);
                const int n = (fbn + q * 8) * 4;
                *reinterpret_cast<uint2*>(&Bh[nxt][fbr][n]) = hi;
                *reinterpret_cast<uint2*>(&Bl[nxt][fbr][n]) = lo;
            }
        }
        __syncthreads();
    }

    float* dst = g_ppart[ks];
#pragma unroll
    for (int nt = 0; nt < 4; nt++) {
        const int n = nBase + w * 32 + nt * 8 + (lane & 3) * 2;
#pragma unroll
        for (int mt = 0; mt < 4; mt++) {
            const int m0 = mBase + mt * 16 + (lane >> 2);
            *reinterpret_cast<float2*>(dst + (size_t)m0 * DIN + n) =
                make_float2(c[mt][nt][0], c[mt][nt][1]);
            *reinterpret_cast<float2*>(dst + (size_t)(m0 + 8) * DIN + n) =
                make_float2(c[mt][nt][2], c[mt][nt][3]);
        }
    }
}

// ---------------- K4b: combine partials + bias -> g_pred ------------------
__global__ __launch_bounds__(256) void k_comb(const float* __restrict__ bG) {
    const int idx = blockIdx.x * 256 + threadIdx.x;
    const int S = BB * NOUT * DIN / 4;
    const float4* p = reinterpret_cast<const float4*>(g_ppart);
    float4 a = p[idx], b2 = p[idx + S], c2 = p[idx + 2 * S], d = p[idx + 3 * S];
    const float4 bg = reinterpret_cast<const float4*>(bG)[idx & (DIN / 4 - 1)];
    reinterpret_cast<float4*>(g_pred)[idx] = make_float4(
        a.x + b2.x + c2.x + d.x + bg.x, a.y + b2.y + c2.y + d.y + bg.y,
        a.z + b2.z + c2.z + d.z + bg.z, a.w + b2.w + c2.w + d.w + bg.w);
}

// ---------------- K5 (TENSOR, round-7 proven): S -> softmax -> phi1 -------
// Grid (it 0..7, b 0..31), 128 thr. Tile 128i x 64j, stage K=16.
__global__ __launch_bounds__(128) void k_sim(const float* __restrict__ x,
                                             const float* __restrict__ bu,
                                             const float* __restrict__ bn) {
    const int i0 = blockIdx.x * 128;
    const int b = blockIdx.y;
    __shared__ __align__(16) uint16_t Ah[2][128][PKP], Al[2][128][PKP];
    __shared__ __align__(16) uint16_t Bh[2][NOUT][PKP], Bl[2][NOUT][PKP];
    const int tid = threadIdx.x, lane = tid & 31, w = tid >> 5;
    const int fbj = tid & 63, fbk = (tid >> 6) * 8;
    const int arow = lane & 15, acol = (lane >> 4) * 8;
    const int brow = ((lane >> 4) & 1) * 8 + (lane & 7), bcol = ((lane >> 3) & 1) * 8;

    const float* Arow = x + ((size_t)b * NI + i0 + tid) * DIN;
    const float* Brow = g_pred + ((size_t)b * NOUT + fbj) * DIN;

    float c[2][8][4];
#pragma unroll
    for (int mt = 0; mt < 2; mt++)
#pragma unroll
        for (int nt = 0; nt < 8; nt++)
#pragma unroll
            for (int e = 0; e < 4; e++) c[mt][nt][e] = 0.f;

    float4 aR[4]; float4 bR[2];
#pragma unroll
    for (int q = 0; q < 4; q++)
        aR[q] = *reinterpret_cast<const float4*>(Arow + q * 4);
#pragma unroll
    for (int q = 0; q < 2; q++)
        bR[q] = *reinterpret_cast<const float4*>(Brow + fbk + q * 4);
    {
#pragma unroll
        for (int q = 0; q < 4; q++) {
            uint2 hi, lo; cvt_split(aR[q], hi, lo);
            *reinterpret_cast<uint2*>(&Ah[0][tid][q * 4]) = hi;
            *reinterpret_cast<uint2*>(&Al[0][tid][q * 4]) = lo;
        }
#pragma unroll
        for (int q = 0; q < 2; q++) {
            uint2 hi, lo; cvt_split(bR[q], hi, lo);
            *reinterpret_cast<uint2*>(&Bh[0][fbj][fbk + q * 4]) = hi;
            *reinterpret_cast<uint2*>(&Bl[0][fbj][fbk + q * 4]) = lo;
        }
    }
    __syncthreads();

    const int NSTG = DIN / 16;
    for (int t = 0; t < NSTG; t++) {
        const int cur = t & 1;
        const bool more = (t + 1 < NSTG);
        if (more) {
            const int d0 = (t + 1) * 16;
#pragma unroll
            for (int q = 0; q < 4; q++)
                aR[q] = *reinterpret_cast<const float4*>(Arow + d0 + q * 4);
#pragma unroll
            for (int q = 0; q < 2; q++)
                bR[q] = *reinterpret_cast<const float4*>(Brow + d0 + fbk + q * 4);
        }
        {
            uint32_t ah[2][4], al[2][4], bh[8][2], bl[8][2];
#pragma unroll
            for (int mt = 0; mt < 2; mt++) {
                const int am = w * 32 + mt * 16 + arow;
                ldsm4(ah[mt][0], ah[mt][1], ah[mt][2], ah[mt][3],
                      smem_u32(&Ah[cur][am][acol]));
                ldsm4(al[mt][0], al[mt][1], al[mt][2], al[mt][3],
                      smem_u32(&Al[cur][am][acol]));
            }
#pragma unroll
            for (int p = 0; p < 4; p++) {
                const int bj = p * 16 + brow;
                ldsm4(bh[2 * p][0], bh[2 * p][1], bh[2 * p + 1][0], bh[2 * p + 1][1],
                      smem_u32(&Bh[cur][bj][bcol]));
                ldsm4(bl[2 * p][0], bl[2 * p][1], bl[2 * p + 1][0], bl[2 * p + 1][1],
                      smem_u32(&Bl[cur][bj][bcol]));
            }
#pragma unroll
            for (int mt = 0; mt < 2; mt++)
#pragma unroll
                for (int nt = 0; nt < 8; nt++) {
                    mma_bf16(c[mt][nt], ah[mt], bh[nt][0], bh[nt][1]);
                    mma_bf16(c[mt][nt], ah[mt], bl[nt][0], bl[nt][1]);
                    mma_bf16(c[mt][nt], al[mt], bh[nt][0], bh[nt][1]);
                }
        }
        if (more) {
            const int nxt = 1 - cur;
#pragma unroll
            for (int q = 0; q < 4; q++) {
                uint2 hi, lo; cvt_split(aR[q], hi, lo);
                *reinterpret_cast<uint2*>(&Ah[nxt][tid][q * 4]) = hi;
                *reinterpret_cast<uint2*>(&Al[nxt][tid][q * 4]) = lo;
            }
#pragma unroll
            for (int q = 0; q < 2; q++) {
                uint2 hi, lo; cvt_split(bR[q], hi, lo);
                *reinterpret_cast<uint2*>(&Bh[nxt][fbj][fbk + q * 4]) = hi;
                *reinterpret_cast<uint2*>(&Bl[nxt][fbj][fbk + q * 4]) = lo;
            }
        }
        __syncthreads();
    }

    const float scale = 0.03125f;  // 1024^-0.5
#pragma unroll
    for (int mt = 0; mt < 2; mt++) {
#pragma unroll
        for (int half = 0; half < 2; half++) {
            const int rg = i0 + w * 32 + mt * 16 + (lane >> 2) + half * 8;
            float v[16];
#pragma unroll
            for (int nt = 0; nt < 8; nt++) {
                v[nt * 2 + 0] = c[mt][nt][half * 2 + 0] * scale;
                v[nt * 2 + 1] = c[mt][nt][half * 2 + 1] * scale;
            }
            float mx = v[0];
#pragma unroll
            for (int q = 1; q < 16; q++) mx = fmaxf(mx, v[q]);
            mx = fmaxf(mx, __shfl_xor_sync(0xffffffffu, mx, 1));
            mx = fmaxf(mx, __shfl_xor_sync(0xffffffffu, mx, 2));
            float e[16], s = 0.f;
#pragma unroll
            for (int q = 0; q < 16; q++) { e[q] = __expf(v[q] - mx); s += e[q]; }
            s += __shfl_xor_sync(0xffffffffu, s, 1);
            s += __shfl_xor_sync(0xffffffffu, s, 2);
            const float inv = 1.f / s;
            const float fa = g_faT[rg * BB + b];
            float* o = g_phi1 + ((size_t)b * NI + rg) * NOUT;
#pragma unroll
            for (int nt = 0; nt < 8; nt++) {
                const int jj = nt * 8 + (lane & 3) * 2;
                const float2 bu2 = *reinterpret_cast<const float2*>(bu + (size_t)rg * NOUT + jj);
                const float2 bn2 = *reinterpret_cast<const float2*>(bn + (size_t)rg * NOUT + jj);
                *reinterpret_cast<float2*>(o + jj) = make_float2(
                    fa * ((bu2.x + bn2.x) * e[nt * 2 + 0] * inv - bn2.x),
                    fa * ((bu2.y + bn2.y) * e[nt * 2 + 1] * inv - bn2.y));
            }
        }
    }
}

// ---------------- K6: transpose phi1 [b][i][j] -> phiT [j][i][b] ----------
__global__ __launch_bounds__(256) void k_tr() {
    const int i = blockIdx.x;
    __shared__ float t[32][65];
    const int tid = threadIdx.x;
#pragma unroll
    for (int q = 0; q < 8; q++) {
        int idx = tid + q * 256;
        int bb = idx >> 6, j = idx & 63;
        t[bb][j] = g_phi1[((size_t)bb * NI + i) * NOUT + j];
    }
    __syncthreads();
#pragma unroll
    for (int q = 0; q < 8; q++) {
        int idx = tid + q * 256;
        int j = idx >> 5, bb = idx & 31;
        g_phiT[((size_t)j * NI + i) * BB + bb] = t[bb][j];
    }
}

// ---------------- launch ---------------------------------------------------
extern "C" void kernel_launch(void* const* d_in, const int* in_sizes, int n_in,
                              void* d_out, int out_size) {
    const float* x  = (const float*)d_in[0];
    const float* WA = (const float*)d_in[1];
    const float* bA = (const float*)d_in[2];
    const float* Wm = (const float*)d_in[3];
    const float* WG = (const float*)d_in[4];
    const float* bG = (const float*)d_in[5];
    const float* bu = (const float*)d_in[6];
    const float* bn = (const float*)d_in[7];
    float* out = (float*)d_out;

    k_fa<<<4096, 256>>>(x, WA, bA);
    k_phi0<<<256, 256>>>(bu, bn);
    k_mem<0><<<dim3(8, 64), 128>>>(Wm, nullptr);
    k_predp<<<dim3(8, 32, 4), 128>>>(WG);
    k_comb<<<BB * NOUT * DIN / 1024, 256>>>(bG);
    k_sim<<<dim3(8, 32), 128>>>(x, bu, bn);
    k_tr<<<NI, 256>>>();
    k_mem<1><<<dim3(8, 64), 128>>>(Wm, out);
}